// round 6
// baseline (speedup 1.0000x reference)
#include <cuda_runtime.h>

#define NN   25000
#define EE0  400000
#define EEL  425000
#define DD   64
#define HH   4
#define CC   64
#define HCX  256
#define LLAY 3
#define NEG  0.2f
#define EPSN 1e-5f

// ---------------- scratch (static device globals; no allocation) ----------------
__device__ float4 g_xl[NN * 64];              // [N][H*C] as float4  (25.6 MB)
__device__ float4 g_xr[NN * 64];              // 25.6 MB
__device__ float  g_h[NN * CC];               // per-layer conv output (pre-norm)
__device__ int    g_rowptr[NN + 1];
__device__ int    g_woff[NN];
__device__ int    g_deg[NN];
__device__ int    g_csrsrc[EEL];
__device__ float  g_colsum[CC], g_colsq[CC];
__device__ float  g_A[CC], g_B[CC];
__device__ float  g_WlT[LLAY * DD * HCX];     // transposed weights [l][d][o]
__device__ float  g_WrT[LLAY * DD * HCX];
__device__ int    g_is64;                     // edge_index dtype flag

// ---------------- dtype sniff: int64 edge_index has zero odd words ----------------
__global__ void k_sniff(const int* __restrict__ ei) {
    __shared__ int s_acc[128];
    int tid = threadIdx.x;
    int acc = 0;
    for (int i = tid; i < 2048; i += 128) acc |= ei[2 * i + 1];
    s_acc[tid] = acc;
    __syncthreads();
    for (int off = 64; off >= 1; off >>= 1) {
        if (tid < off) s_acc[tid] |= s_acc[tid + off];
        __syncthreads();
    }
    if (tid == 0) g_is64 = (s_acc[0] == 0) ? 1 : 0;
}

__device__ __forceinline__ int load_src(const int* ei, int e, int is64) {
    return is64 ? ei[2 * e] : ei[e];
}
__device__ __forceinline__ int load_dst(const int* ei, int e, int is64) {
    return is64 ? ei[2 * (EE0 + e)] : ei[EE0 + e];
}

// ---------------- weight transpose (once) ----------------
__global__ void k_transpose(const float* __restrict__ Wl, const float* __restrict__ Wr) {
    int idx = blockIdx.x * blockDim.x + threadIdx.x;
    int tot = LLAY * HCX * DD;
    if (idx >= tot) return;
    int l = idx / (HCX * DD);
    int r = idx - l * (HCX * DD);
    int o = r / DD;
    int d = r - o * DD;
    g_WlT[l * HCX * DD + d * HCX + o] = Wl[idx];
    g_WrT[l * HCX * DD + d * HCX + o] = Wr[idx];
}

// ---------------- CSR build ----------------
__global__ void k_zero_deg() {
    int i = blockIdx.x * blockDim.x + threadIdx.x;
    if (i < NN) g_deg[i] = 0;
}

__global__ void k_count(const int* __restrict__ ei) {
    int e = blockIdx.x * blockDim.x + threadIdx.x;
    if (e >= EEL) return;
    int is64 = g_is64;
    int dst = (e < EE0) ? load_dst(ei, e, is64) : (e - EE0);
    if ((unsigned)dst < (unsigned)NN)
        atomicAdd(&g_deg[dst], 1);
}

__global__ __launch_bounds__(1024) void k_scan() {
    __shared__ int sp[1024];
    int i = threadIdx.x;
    const int CH = 25;                   // 1024*25 = 25600 >= 25000
    int beg = i * CH;
    int end = beg + CH; if (end > NN) end = NN;
    int s = 0;
    for (int j = beg; j < end; ++j) s += g_deg[j];
    sp[i] = s;
    __syncthreads();
    for (int off = 1; off < 1024; off <<= 1) {
        int v = (i >= off) ? sp[i - off] : 0;
        __syncthreads();
        sp[i] += v;
        __syncthreads();
    }
    int run = sp[i] - s;                 // exclusive prefix
    for (int j = beg; j < end; ++j) {
        g_rowptr[j] = run;
        g_woff[j]   = run;
        run += g_deg[j];
    }
    if (i == 0) g_rowptr[NN] = EEL;
}

__global__ void k_scatter(const int* __restrict__ ei) {
    int e = blockIdx.x * blockDim.x + threadIdx.x;
    if (e >= EEL) return;
    int is64 = g_is64;
    int src, dst;
    if (e < EE0) { src = load_src(ei, e, is64); dst = load_dst(ei, e, is64); }
    else         { src = dst = e - EE0; }
    if ((unsigned)dst >= (unsigned)NN || (unsigned)src >= (unsigned)NN) return;
    int pos = atomicAdd(&g_woff[dst], 1);
    g_csrsrc[pos] = src;
}

// ---------------- projections (norm of previous layer fused into the load) ----------------
#define NB 20
__global__ __launch_bounds__(256) void k_proj(const float* __restrict__ xext,
                                              const float* __restrict__ bl,
                                              const float* __restrict__ br,
                                              int l) {
    __shared__ float xs[NB * DD];                  // 5 KB
    int node0 = blockIdx.x * NB;                   // 25000 % 20 == 0
    int tid = threadIdx.x;
    if (l == 0) {
        for (int i = tid; i < NB * DD; i += 256)
            xs[i] = xext[node0 * DD + i];
    } else {
        for (int i = tid; i < NB * DD; i += 256) {
            int c = i & 63;                        // DD == 64
            xs[i] = fmaf(g_h[node0 * DD + i], g_A[c], g_B[c]);
        }
    }
    __syncthreads();

    const float* wl = g_WlT + l * DD * HCX;
    const float* wr = g_WrT + l * DD * HCX;
    float accl[NB], accr[NB];
#pragma unroll
    for (int n = 0; n < NB; ++n) { accl[n] = 0.f; accr[n] = 0.f; }

#pragma unroll 4
    for (int d = 0; d < DD; ++d) {
        float a = wl[d * HCX + tid];
        float b = wr[d * HCX + tid];
#pragma unroll
        for (int n = 0; n < NB; ++n) {
            float xv = xs[n * DD + d];
            accl[n] = fmaf(a, xv, accl[n]);
            accr[n] = fmaf(b, xv, accr[n]);
        }
    }
    float bli = bl[l * HCX + tid], bri = br[l * HCX + tid];
    float* xlp = (float*)g_xl;
    float* xrp = (float*)g_xr;
#pragma unroll
    for (int n = 0; n < NB; ++n) {
        int node = node0 + n;
        xlp[node * HCX + tid] = accl[n] + bli;
        xrp[node * HCX + tid] = accr[n] + bri;
    }
}

// ---------------- fused single-pass GAT: one WARP per node, online softmax ----------------
__device__ __forceinline__ float lrelu(float v) { return v > 0.f ? v : NEG * v; }

__device__ __forceinline__ float edge_logit(const float4& a0, const float4& a1,
                                            const float4& xr0, const float4& xr1,
                                            const float4& at0, const float4& at1) {
    float p = 0.f;
    p = fmaf(at0.x, lrelu(a0.x + xr0.x), p);
    p = fmaf(at0.y, lrelu(a0.y + xr0.y), p);
    p = fmaf(at0.z, lrelu(a0.z + xr0.z), p);
    p = fmaf(at0.w, lrelu(a0.w + xr0.w), p);
    p = fmaf(at1.x, lrelu(a1.x + xr1.x), p);
    p = fmaf(at1.y, lrelu(a1.y + xr1.y), p);
    p = fmaf(at1.z, lrelu(a1.z + xr1.z), p);
    p = fmaf(at1.w, lrelu(a1.w + xr1.w), p);
    p += __shfl_xor_sync(0xffffffffu, p, 1);
    p += __shfl_xor_sync(0xffffffffu, p, 2);
    p += __shfl_xor_sync(0xffffffffu, p, 4);
    return p;     // uniform within each 8-lane head group
}

__global__ __launch_bounds__(256) void k_gat(const float* __restrict__ att,
                                             const float* __restrict__ cbias,
                                             int l) {
    int tid  = threadIdx.x;
    int lane = tid & 31;
    int w    = tid >> 5;
    int node = blockIdx.x * 8 + w;           // 3125 blocks * 8 = 25000 exactly
    int row0 = g_rowptr[node];
    int deg  = g_rowptr[node + 1] - row0;

    const float4* att4 = (const float4*)(att + l * HCX);
    float4 at0 = att4[lane * 2];
    float4 at1 = att4[lane * 2 + 1];
    float4 xr0 = g_xr[node * 64 + lane * 2];
    float4 xr1 = g_xr[node * 64 + lane * 2 + 1];

    float m = -1e30f, den = 0.f;
    float acc[8];
#pragma unroll
    for (int j = 0; j < 8; ++j) acc[j] = 0.f;

    int k = 0;
    for (; k + 2 <= deg; k += 2) {           // 2-wide: batched loads, one rescale
        int s0 = g_csrsrc[row0 + k];
        int s1 = g_csrsrc[row0 + k + 1];
        float4 a0 = g_xl[s0 * 64 + lane * 2];
        float4 a1 = g_xl[s0 * 64 + lane * 2 + 1];
        float4 b0 = g_xl[s1 * 64 + lane * 2];
        float4 b1 = g_xl[s1 * 64 + lane * 2 + 1];
        float p0 = edge_logit(a0, a1, xr0, xr1, at0, at1);
        float p1 = edge_logit(b0, b1, xr0, xr1, at0, at1);
        float mn  = fmaxf(m, fmaxf(p0, p1));
        float fac = __expf(m - mn);
        float w0  = __expf(p0 - mn);
        float w1  = __expf(p1 - mn);
        m = mn;
        den = fmaf(den, fac, w0 + w1);
        acc[0] = fmaf(acc[0], fac, fmaf(w0, a0.x, w1 * b0.x));
        acc[1] = fmaf(acc[1], fac, fmaf(w0, a0.y, w1 * b0.y));
        acc[2] = fmaf(acc[2], fac, fmaf(w0, a0.z, w1 * b0.z));
        acc[3] = fmaf(acc[3], fac, fmaf(w0, a0.w, w1 * b0.w));
        acc[4] = fmaf(acc[4], fac, fmaf(w0, a1.x, w1 * b1.x));
        acc[5] = fmaf(acc[5], fac, fmaf(w0, a1.y, w1 * b1.y));
        acc[6] = fmaf(acc[6], fac, fmaf(w0, a1.z, w1 * b1.z));
        acc[7] = fmaf(acc[7], fac, fmaf(w0, a1.w, w1 * b1.w));
    }
    if (k < deg) {
        int s0 = g_csrsrc[row0 + k];
        float4 a0 = g_xl[s0 * 64 + lane * 2];
        float4 a1 = g_xl[s0 * 64 + lane * 2 + 1];
        float p0 = edge_logit(a0, a1, xr0, xr1, at0, at1);
        float mn  = fmaxf(m, p0);
        float fac = __expf(m - mn);
        float w0  = __expf(p0 - mn);
        m = mn;
        den = fmaf(den, fac, w0);
        acc[0] = fmaf(acc[0], fac, w0 * a0.x);
        acc[1] = fmaf(acc[1], fac, w0 * a0.y);
        acc[2] = fmaf(acc[2], fac, w0 * a0.z);
        acc[3] = fmaf(acc[3], fac, w0 * a0.w);
        acc[4] = fmaf(acc[4], fac, w0 * a1.x);
        acc[5] = fmaf(acc[5], fac, w0 * a1.y);
        acc[6] = fmaf(acc[6], fac, w0 * a1.z);
        acc[7] = fmaf(acc[7], fac, w0 * a1.w);
    }

    // normalize per head, then sum heads across lane bits 3,4 (shfl)
    float inv = 1.0f / den;
#pragma unroll
    for (int j = 0; j < 8; ++j) {
        float v = acc[j] * inv;
        v += __shfl_xor_sync(0xffffffffu, v, 8);
        v += __shfl_xor_sync(0xffffffffu, v, 16);
        acc[j] = v;                        // lane L holds sum_h for c=(L&7)*8+j
    }
    if (lane < 8) {
        float4 o0, o1;
        const float* cb = cbias + l * CC + lane * 8;
        o0.x = 0.25f * acc[0] + cb[0];
        o0.y = 0.25f * acc[1] + cb[1];
        o0.z = 0.25f * acc[2] + cb[2];
        o0.w = 0.25f * acc[3] + cb[3];
        o1.x = 0.25f * acc[4] + cb[4];
        o1.y = 0.25f * acc[5] + cb[5];
        o1.z = 0.25f * acc[6] + cb[6];
        o1.w = 0.25f * acc[7] + cb[7];
        float4* hp = (float4*)(g_h + node * CC + lane * 8);
        hp[0] = o0;
        hp[1] = o1;
    }
}

// ---------------- GraphNorm stats ----------------
__global__ void k_zero_stats() {
    int t = threadIdx.x;
    if (t < CC) { g_colsum[t] = 0.f; g_colsq[t] = 0.f; }
}

__global__ __launch_bounds__(256) void k_colstats() {
    int tid = threadIdx.x;
    int c = tid & 63;
    float s = 0.f, q = 0.f;
    int stride = gridDim.x * blockDim.x;
    for (int idx = blockIdx.x * blockDim.x + tid; idx < NN * CC; idx += stride) {
        float v = g_h[idx];
        s += v;
        q = fmaf(v, v, q);
    }
    __shared__ float ss[256], sq[256];
    ss[tid] = s; sq[tid] = q;
    __syncthreads();
    if (tid < 128) { ss[tid] += ss[tid + 128]; sq[tid] += sq[tid + 128]; }
    __syncthreads();
    if (tid < 64) {
        atomicAdd(&g_colsum[c], ss[tid] + ss[tid + 64]);
        atomicAdd(&g_colsq[c],  sq[tid] + sq[tid + 64]);
    }
}

__global__ void k_finalize(const float* __restrict__ gw,
                           const float* __restrict__ gs,
                           const float* __restrict__ gb, int l) {
    int c = threadIdx.x;
    if (c >= CC) return;
    float invn = 1.0f / (float)NN;
    float mu = g_colsum[c] * invn;
    float m2 = g_colsq[c]  * invn;
    float sc = gs[l * CC + c];
    float var = m2 - 2.f * sc * mu * mu + sc * sc * mu * mu;
    float rstd = rsqrtf(var + EPSN);
    float A = rstd * gw[l * CC + c];
    g_A[c] = A;
    g_B[c] = gb[l * CC + c] - sc * mu * A;
}

__global__ __launch_bounds__(256) void k_norm(float* __restrict__ out) {
    int stride = gridDim.x * blockDim.x;
    for (int idx = blockIdx.x * blockDim.x + threadIdx.x; idx < NN * CC; idx += stride) {
        int c = idx & 63;
        out[idx] = fmaf(g_h[idx], g_A[c], g_B[c]);
    }
}

// ---------------- launch ----------------
extern "C" void kernel_launch(void* const* d_in, const int* in_sizes, int n_in,
                              void* d_out, int out_size) {
    const float* x   = (const float*)d_in[0];
    const int*   ei  = (const int*)d_in[1];
    const float* Wl  = (const float*)d_in[2];
    const float* bl  = (const float*)d_in[3];
    const float* Wr  = (const float*)d_in[4];
    const float* br  = (const float*)d_in[5];
    const float* att = (const float*)d_in[6];
    const float* cb  = (const float*)d_in[7];
    const float* gw  = (const float*)d_in[8];
    const float* gs  = (const float*)d_in[9];
    const float* gb  = (const float*)d_in[10];
    float* out = (float*)d_out;

    k_sniff<<<1, 128>>>(ei);
    k_transpose<<<(LLAY * HCX * DD + 255) / 256, 256>>>(Wl, Wr);
    k_zero_deg<<<(NN + 255) / 256, 256>>>();
    k_count<<<(EEL + 255) / 256, 256>>>(ei);
    k_scan<<<1, 1024>>>();
    k_scatter<<<(EEL + 255) / 256, 256>>>(ei);

    for (int l = 0; l < LLAY; ++l) {
        k_proj<<<NN / NB, 256>>>(x, bl, br, l);   // l>0: applies previous norm on load
        k_gat<<<NN / 8, 256>>>(att, cb, l);
        k_zero_stats<<<1, 64>>>();
        k_colstats<<<296, 256>>>();
        k_finalize<<<1, 64>>>(gw, gs, gb, l);
    }
    k_norm<<<296, 256>>>(out);                    // final layer norm -> output
}

// round 7
// speedup vs baseline: 1.0833x; 1.0833x over previous
#include <cuda_runtime.h>

#define NN   25000
#define EE0  400000
#define EEL  425000
#define DD   64
#define HH   4
#define CC   64
#define HCX  256
#define LLAY 3
#define NEG  0.2f
#define EPSN 1e-5f

// ---------------- scratch (static device globals; no allocation) ----------------
__device__ float4 g_xl[NN * 64];              // [N][H*C] as float4  (25.6 MB)
__device__ float4 g_xr[NN * 64];              // 25.6 MB
__device__ float  g_h[NN * CC];               // per-layer conv output (pre-norm)
__device__ int    g_rowptr[NN + 1];
__device__ int    g_woff[NN];
__device__ int    g_deg[NN];
__device__ int    g_csrsrc[EEL];
__device__ float  g_colsum[LLAY * CC], g_colsq[LLAY * CC];   // per-layer stats
__device__ float  g_A[LLAY * CC], g_B[LLAY * CC];            // per-layer norm affine
__device__ float  g_WlT[LLAY * DD * HCX];     // transposed weights [l][d][o]
__device__ float  g_WrT[LLAY * DD * HCX];
__device__ int    g_is64;                     // edge_index dtype flag

// ---------------- init: sniff dtype + zero deg + zero all per-layer stats ----------------
__global__ void k_init(const int* __restrict__ ei) {
    int tid = threadIdx.x;
    int gidx = blockIdx.x * blockDim.x + tid;
    // zero degree (grid-stride over all blocks)
    for (int i = gidx; i < NN; i += gridDim.x * blockDim.x) g_deg[i] = 0;
    if (blockIdx.x == 0) {
        // zero per-layer stats
        for (int i = tid; i < LLAY * CC; i += blockDim.x) {
            g_colsum[i] = 0.f;
            g_colsq[i]  = 0.f;
        }
        // dtype sniff: int64 edge_index (values < 25000) has zero odd words
        __shared__ int s_acc[256];
        int acc = 0;
        for (int i = tid; i < 2048; i += 256) acc |= ei[2 * i + 1];
        s_acc[tid] = acc;
        __syncthreads();
        for (int off = 128; off >= 1; off >>= 1) {
            if (tid < off) s_acc[tid] |= s_acc[tid + off];
            __syncthreads();
        }
        if (tid == 0) g_is64 = (s_acc[0] == 0) ? 1 : 0;
    }
}

__device__ __forceinline__ int load_src(const int* ei, int e, int is64) {
    return is64 ? ei[2 * e] : ei[e];
}
__device__ __forceinline__ int load_dst(const int* ei, int e, int is64) {
    return is64 ? ei[2 * (EE0 + e)] : ei[EE0 + e];
}

// ---------------- CSR build ----------------
__global__ void k_count(const int* __restrict__ ei) {
    int e = blockIdx.x * blockDim.x + threadIdx.x;
    if (e >= EEL) return;
    int is64 = g_is64;
    int dst = (e < EE0) ? load_dst(ei, e, is64) : (e - EE0);
    if ((unsigned)dst < (unsigned)NN)
        atomicAdd(&g_deg[dst], 1);
}

__global__ __launch_bounds__(1024) void k_scan() {
    __shared__ int sp[1024];
    int i = threadIdx.x;
    const int CH = 25;                   // 1024*25 = 25600 >= 25000
    int beg = i * CH;
    int end = beg + CH; if (end > NN) end = NN;
    int s = 0;
    for (int j = beg; j < end; ++j) s += g_deg[j];
    sp[i] = s;
    __syncthreads();
    for (int off = 1; off < 1024; off <<= 1) {
        int v = (i >= off) ? sp[i - off] : 0;
        __syncthreads();
        sp[i] += v;
        __syncthreads();
    }
    int run = sp[i] - s;                 // exclusive prefix
    for (int j = beg; j < end; ++j) {
        g_rowptr[j] = run;
        g_woff[j]   = run;
        run += g_deg[j];
    }
    if (i == 0) g_rowptr[NN] = EEL;
}

__global__ void k_scatter(const int* __restrict__ ei) {
    int e = blockIdx.x * blockDim.x + threadIdx.x;
    if (e >= EEL) return;
    int is64 = g_is64;
    int src, dst;
    if (e < EE0) { src = load_src(ei, e, is64); dst = load_dst(ei, e, is64); }
    else         { src = dst = e - EE0; }
    if ((unsigned)dst >= (unsigned)NN || (unsigned)src >= (unsigned)NN) return;
    int pos = atomicAdd(&g_woff[dst], 1);
    g_csrsrc[pos] = src;
}

// ---------------- weight transpose (once, placed just before layer loop) ----------------
__global__ void k_transpose(const float* __restrict__ Wl, const float* __restrict__ Wr) {
    int idx = blockIdx.x * blockDim.x + threadIdx.x;
    int tot = LLAY * HCX * DD;
    if (idx >= tot) return;
    int l = idx / (HCX * DD);
    int r = idx - l * (HCX * DD);
    int o = r / DD;
    int d = r - o * DD;
    g_WlT[l * HCX * DD + d * HCX + o] = Wl[idx];
    g_WrT[l * HCX * DD + d * HCX + o] = Wr[idx];
}

// ---------------- projections (norm of previous layer fused into the load) ----------------
#define NB 20
__global__ __launch_bounds__(256) void k_proj(const float* __restrict__ xext,
                                              const float* __restrict__ bl,
                                              const float* __restrict__ br,
                                              int l) {
    __shared__ float xs[NB * DD];                  // 5 KB
    int node0 = blockIdx.x * NB;                   // 25000 % 20 == 0
    int tid = threadIdx.x;
    if (l == 0) {
        for (int i = tid; i < NB * DD; i += 256)
            xs[i] = xext[node0 * DD + i];
    } else {
        const float* Ap = g_A + (l - 1) * CC;
        const float* Bp = g_B + (l - 1) * CC;
        for (int i = tid; i < NB * DD; i += 256) {
            int c = i & 63;                        // DD == 64
            xs[i] = fmaf(g_h[node0 * DD + i], Ap[c], Bp[c]);
        }
    }
    __syncthreads();

    const float* wl = g_WlT + l * DD * HCX;
    const float* wr = g_WrT + l * DD * HCX;
    float accl[NB], accr[NB];
#pragma unroll
    for (int n = 0; n < NB; ++n) { accl[n] = 0.f; accr[n] = 0.f; }

#pragma unroll 4
    for (int d = 0; d < DD; ++d) {
        float a = wl[d * HCX + tid];
        float b = wr[d * HCX + tid];
#pragma unroll
        for (int n = 0; n < NB; ++n) {
            float xv = xs[n * DD + d];
            accl[n] = fmaf(a, xv, accl[n]);
            accr[n] = fmaf(b, xv, accr[n]);
        }
    }
    float bli = bl[l * HCX + tid], bri = br[l * HCX + tid];
    float* xlp = (float*)g_xl;
    float* xrp = (float*)g_xr;
#pragma unroll
    for (int n = 0; n < NB; ++n) {
        int node = node0 + n;
        xlp[node * HCX + tid] = accl[n] + bli;
        xrp[node * HCX + tid] = accr[n] + bri;
    }
}

// ---------------- fused single-pass GAT: online softmax, one BLOCK per node (R5) ----------------
__device__ __forceinline__ float lrelu(float v) { return v > 0.f ? v : NEG * v; }

__global__ __launch_bounds__(256) void k_gat(const float* __restrict__ att,
                                             const float* __restrict__ cbias,
                                             int l) {
    int node = blockIdx.x;
    int tid  = threadIdx.x;
    int lane = tid & 31;
    int w    = tid >> 5;
    int row0 = g_rowptr[node];
    int deg  = g_rowptr[node + 1] - row0;

    __shared__ float s_m[32];          // [warp][head]
    __shared__ float s_d[32];
    __shared__ float s_acc[8 * 256];   // per-warp channel accumulators (8 KB)
    __shared__ float s_red[256];

    const float4* att4 = (const float4*)(att + l * HCX);
    float4 at0 = att4[lane * 2];
    float4 at1 = att4[lane * 2 + 1];
    float4 xr0 = g_xr[node * 64 + lane * 2];
    float4 xr1 = g_xr[node * 64 + lane * 2 + 1];

    // per-lane running softmax state over this warp's edge subset
    float m = -1e30f, den = 0.f;
    float acc[8];
#pragma unroll
    for (int j = 0; j < 8; ++j) acc[j] = 0.f;

    for (int k = w; k < deg; k += 8) {
        int s = g_csrsrc[row0 + k];
        float4 a0 = g_xl[s * 64 + lane * 2];
        float4 a1 = g_xl[s * 64 + lane * 2 + 1];
        float p = 0.f;
        p = fmaf(at0.x, lrelu(a0.x + xr0.x), p);
        p = fmaf(at0.y, lrelu(a0.y + xr0.y), p);
        p = fmaf(at0.z, lrelu(a0.z + xr0.z), p);
        p = fmaf(at0.w, lrelu(a0.w + xr0.w), p);
        p = fmaf(at1.x, lrelu(a1.x + xr1.x), p);
        p = fmaf(at1.y, lrelu(a1.y + xr1.y), p);
        p = fmaf(at1.z, lrelu(a1.z + xr1.z), p);
        p = fmaf(at1.w, lrelu(a1.w + xr1.w), p);
        // reduce across the 8 lanes of this head group
        p += __shfl_xor_sync(0xffffffffu, p, 1);
        p += __shfl_xor_sync(0xffffffffu, p, 2);
        p += __shfl_xor_sync(0xffffffffu, p, 4);
        // online softmax update (uniform within each 8-lane head group)
        float mn  = fmaxf(m, p);
        float fac = __expf(m - mn);
        float wgt = __expf(p - mn);
        m = mn;
        den = fmaf(den, fac, wgt);
        acc[0] = fmaf(acc[0], fac, wgt * a0.x);
        acc[1] = fmaf(acc[1], fac, wgt * a0.y);
        acc[2] = fmaf(acc[2], fac, wgt * a0.z);
        acc[3] = fmaf(acc[3], fac, wgt * a0.w);
        acc[4] = fmaf(acc[4], fac, wgt * a1.x);
        acc[5] = fmaf(acc[5], fac, wgt * a1.y);
        acc[6] = fmaf(acc[6], fac, wgt * a1.z);
        acc[7] = fmaf(acc[7], fac, wgt * a1.w);
    }

    int h = lane >> 3;
    if ((lane & 7) == 0) { s_m[w * 4 + h] = m; s_d[w * 4 + h] = den; }
#pragma unroll
    for (int j = 0; j < 8; ++j)
        s_acc[w * 256 + lane * 8 + j] = acc[j];
    __syncthreads();

    // combine 8 warps: thread tid owns channel tid, head hh = tid>>6
    int hh = tid >> 6;
    float M = -1e30f;
#pragma unroll
    for (int ww = 0; ww < 8; ++ww) M = fmaxf(M, s_m[ww * 4 + hh]);
    float num = 0.f, D = 0.f;
#pragma unroll
    for (int ww = 0; ww < 8; ++ww) {
        float f = __expf(s_m[ww * 4 + hh] - M);
        num = fmaf(f, s_acc[ww * 256 + tid], num);
        D   = fmaf(f, s_d[ww * 4 + hh], D);
    }
    float val = num / D;
    s_red[tid] = val;
    __syncthreads();
    if (tid < 64) {
        float sum = s_red[tid] + s_red[tid + 64] + s_red[tid + 128] + s_red[tid + 192];
        g_h[node * CC + tid] = 0.25f * sum + cbias[l * CC + tid];
    }
}

// ---------------- GraphNorm stats ----------------
__global__ __launch_bounds__(256) void k_colstats(int l) {
    int tid = threadIdx.x;
    int c = tid & 63;
    float s = 0.f, q = 0.f;
    int stride = gridDim.x * blockDim.x;
    for (int idx = blockIdx.x * blockDim.x + tid; idx < NN * CC; idx += stride) {
        float v = g_h[idx];
        s += v;
        q = fmaf(v, v, q);
    }
    __shared__ float ss[256], sq[256];
    ss[tid] = s; sq[tid] = q;
    __syncthreads();
    if (tid < 128) { ss[tid] += ss[tid + 128]; sq[tid] += sq[tid + 128]; }
    __syncthreads();
    if (tid < 64) {
        atomicAdd(&g_colsum[l * CC + c], ss[tid] + ss[tid + 64]);
        atomicAdd(&g_colsq[l * CC + c],  sq[tid] + sq[tid + 64]);
    }
}

__global__ void k_finalize(const float* __restrict__ gw,
                           const float* __restrict__ gs,
                           const float* __restrict__ gb, int l) {
    int c = threadIdx.x;
    if (c >= CC) return;
    float invn = 1.0f / (float)NN;
    float mu = g_colsum[l * CC + c] * invn;
    float m2 = g_colsq[l * CC + c]  * invn;
    float sc = gs[l * CC + c];
    float var = m2 - 2.f * sc * mu * mu + sc * sc * mu * mu;
    float rstd = rsqrtf(var + EPSN);
    float A = rstd * gw[l * CC + c];
    g_A[l * CC + c] = A;
    g_B[l * CC + c] = gb[l * CC + c] - sc * mu * A;
}

__global__ __launch_bounds__(256) void k_norm(float* __restrict__ out) {
    const float* Ap = g_A + (LLAY - 1) * CC;
    const float* Bp = g_B + (LLAY - 1) * CC;
    int stride = gridDim.x * blockDim.x;
    for (int idx = blockIdx.x * blockDim.x + threadIdx.x; idx < NN * CC; idx += stride) {
        int c = idx & 63;
        out[idx] = fmaf(g_h[idx], Ap[c], Bp[c]);
    }
}

// ---------------- launch ----------------
extern "C" void kernel_launch(void* const* d_in, const int* in_sizes, int n_in,
                              void* d_out, int out_size) {
    const float* x   = (const float*)d_in[0];
    const int*   ei  = (const int*)d_in[1];
    const float* Wl  = (const float*)d_in[2];
    const float* bl  = (const float*)d_in[3];
    const float* Wr  = (const float*)d_in[4];
    const float* br  = (const float*)d_in[5];
    const float* att = (const float*)d_in[6];
    const float* cb  = (const float*)d_in[7];
    const float* gw  = (const float*)d_in[8];
    const float* gs  = (const float*)d_in[9];
    const float* gb  = (const float*)d_in[10];
    float* out = (float*)d_out;

    k_init<<<98, 256>>>(ei);
    k_count<<<(EEL + 255) / 256, 256>>>(ei);
    k_scan<<<1, 1024>>>();
    k_scatter<<<(EEL + 255) / 256, 256>>>(ei);
    k_transpose<<<(LLAY * HCX * DD + 255) / 256, 256>>>(Wl, Wr);

    for (int l = 0; l < LLAY; ++l) {
        k_proj<<<NN / NB, 256>>>(x, bl, br, l);   // l>0: applies previous norm on load
        k_gat<<<NN, 256>>>(att, cb, l);
        k_colstats<<<296, 256>>>(l);
        k_finalize<<<1, 64>>>(gw, gs, gb, l);
    }
    k_norm<<<296, 256>>>(out);                    // final layer norm -> output
}